// round 11
// baseline (speedup 1.0000x reference)
#include <cuda_runtime.h>
#include <cstdint>

#define MD 2048
#define ND 8192
#define KD 30522
#define KP 30528              // K padded to 16
#define TK 32
#define SPC 0.001

#define HID_OFF   62509056LL
#define SCAL_OFF  79286272LL

typedef unsigned long long u64;
typedef uint32_t u32;

#define NT    1908            // KP/16 k-tiles
#define SMP   20              // smem k-stride (16 + 4 pad): conflict-free frag loads
#define PLF   2560            // floats per plane (128*20)
#define SMEMB (8 * PLF * 4)   // 2 stages x 4 planes = 81920 B

// ---- device scratch (static globals; no allocations) ----
__device__ float  g_H[(size_t)MD * ND];
__device__ float  g_inv[ND];
__device__ int    g_ti[MD * TK];
__device__ float  g_tv[MD * TK];
__device__ double g_sse, g_sab;
__device__ int    g_act;

__global__ void k_init() { g_sse = 0.0; g_sab = 0.0; g_act = 0; }

// ---- tf32 + mma helpers (compute_103-safe: Ampere-era PTX only) ----
__device__ __forceinline__ float t32(float x) {
    u32 r; asm("cvt.rna.tf32.f32 %0,%1;" : "=r"(r) : "f"(x));
    return __uint_as_float(r);
}
__device__ __forceinline__ u32 U(float x) { return __float_as_uint(x); }
__device__ __forceinline__ void mma8(float* d, const u32* a, const u32* b) {
    asm volatile(
        "mma.sync.aligned.m16n8k8.row.col.f32.tf32.tf32.f32 "
        "{%0,%1,%2,%3},{%4,%5,%6,%7},{%8,%9},{%0,%1,%2,%3};"
        : "+f"(d[0]), "+f"(d[1]), "+f"(d[2]), "+f"(d[3])
        : "r"(a[0]), "r"(a[1]), "r"(a[2]), "r"(a[3]), "r"(b[0]), "r"(b[1]));
}

// ================= encode GEMM: H = X @ W_enc + b_enc (3xTF32 mma.sync) ===========
// CTA 128x128, BK=16, 256 thr (8 warps, warp tile 64x32), double-buffered smem,
// on-the-fly fp32 -> (hi,lo) tf32 plane split, chunked accumulation (64 k-tiles).
__global__ __launch_bounds__(256, 1) void k_enc_mma(const float* __restrict__ X,
                                                    const float* __restrict__ W,
                                                    const float* __restrict__ Be) {
    extern __shared__ float sm[];
    const int tid = threadIdx.x;
    const int warp = tid >> 5, lane = tid & 31;
    const int wm = warp >> 2, wn = warp & 3;        // warp grid 2x4
    const int g = lane >> 2, tq = lane & 3;
    const int m0 = blockIdx.x * 128, n0 = blockIdx.y * 128;

    float2 av[4]; float4 wv[2];                      // staged global loads
    float ch[4][4][4], tt[4][4][4];
#pragma unroll
    for (int i = 0; i < 4; i++)
#pragma unroll
        for (int j = 0; j < 4; j++)
#pragma unroll
            for (int q = 0; q < 4; q++) { ch[i][j][q] = 0.f; tt[i][j][q] = 0.f; }

    auto ldg = [&](int t) {
        int k0 = t * 16;
#pragma unroll
        for (int i = 0; i < 4; i++) {                // A: 128 x 16 as float2
            int idx = tid + 256 * i;
            int row = idx >> 3, gk = k0 + (idx & 7) * 2;
            av[i] = (gk < KD) ? *(const float2*)(X + (size_t)(m0 + row) * KD + gk)
                              : make_float2(0.f, 0.f);
        }
#pragma unroll
        for (int i = 0; i < 2; i++) {                // W: 16 x 128 as float4
            int idx = tid + 256 * i;
            int r = idx >> 5, gk = k0 + r, c4 = idx & 31;
            wv[i] = (gk < KD) ? *(const float4*)(W + (size_t)gk * ND + n0 + c4 * 4)
                              : make_float4(0.f, 0.f, 0.f, 0.f);
        }
    };
    auto sts = [&](int s) {
        float* A1 = sm + s * 4 * PLF;
        float* A2 = A1 + PLF;
        float* B1 = A2 + PLF;
        float* B2 = B1 + PLF;
#pragma unroll
        for (int i = 0; i < 4; i++) {
            int idx = tid + 256 * i;
            int row = idx >> 3, col = (idx & 7) * 2;
            float hx = t32(av[i].x), hy = t32(av[i].y);
            *(float2*)(A1 + row * SMP + col) = make_float2(hx, hy);
            *(float2*)(A2 + row * SMP + col) =
                make_float2(t32(av[i].x - hx), t32(av[i].y - hy));
        }
#pragma unroll
        for (int i = 0; i < 2; i++) {                // transpose to [n][k]
            int idx = tid + 256 * i;
            int r = idx >> 5, n = (idx & 31) * 4;
            float vv[4] = {wv[i].x, wv[i].y, wv[i].z, wv[i].w};
#pragma unroll
            for (int j = 0; j < 4; j++) {
                float h = t32(vv[j]);
                B1[(n + j) * SMP + r] = h;
                B2[(n + j) * SMP + r] = t32(vv[j] - h);
            }
        }
    };
    auto comp = [&](int s) {
        const float* A1 = sm + s * 4 * PLF;
        const float* A2 = A1 + PLF;
        const float* B1 = A2 + PLF;
        const float* B2 = B1 + PLF;
#pragma unroll
        for (int c = 0; c < 16; c += 8) {
            u32 bf[2][4][2];
#pragma unroll
            for (int nt = 0; nt < 4; nt++) {
                int n = (wn * 32 + nt * 8 + g) * SMP + c + tq;
                bf[0][nt][0] = U(B1[n]); bf[0][nt][1] = U(B1[n + 4]);
                bf[1][nt][0] = U(B2[n]); bf[1][nt][1] = U(B2[n + 4]);
            }
            u32 af[4][4];
#pragma unroll
            for (int mt = 0; mt < 4; mt++) {         // A1 fragments
                int r = (wm * 64 + mt * 16 + g) * SMP + c + tq;
                af[mt][0] = U(A1[r]);            af[mt][1] = U(A1[r + 8 * SMP]);
                af[mt][2] = U(A1[r + 4]);        af[mt][3] = U(A1[r + 8 * SMP + 4]);
            }
#pragma unroll
            for (int mt = 0; mt < 4; mt++)
#pragma unroll
                for (int nt = 0; nt < 4; nt++) {
                    mma8(ch[mt][nt], af[mt], bf[0][nt]);   // hi*hi
                    mma8(ch[mt][nt], af[mt], bf[1][nt]);   // hi*lo
                }
#pragma unroll
            for (int mt = 0; mt < 4; mt++) {         // A2 fragments (reuse buffer)
                int r = (wm * 64 + mt * 16 + g) * SMP + c + tq;
                af[mt][0] = U(A2[r]);            af[mt][1] = U(A2[r + 8 * SMP]);
                af[mt][2] = U(A2[r + 4]);        af[mt][3] = U(A2[r + 8 * SMP + 4]);
            }
#pragma unroll
            for (int mt = 0; mt < 4; mt++)
#pragma unroll
                for (int nt = 0; nt < 4; nt++)
                    mma8(ch[mt][nt], af[mt], bf[0][nt]);   // lo*hi
        }
    };

    ldg(0); sts(0); __syncthreads();
    for (int t = 0; t < NT; t++) {
        int s = t & 1;
        if (t + 1 < NT) ldg(t + 1);
        comp(s);
        if ((t & 63) == 63 || t == NT - 1) {
#pragma unroll
            for (int i = 0; i < 4; i++)
#pragma unroll
                for (int j = 0; j < 4; j++)
#pragma unroll
                    for (int q = 0; q < 4; q++) { tt[i][j][q] += ch[i][j][q]; ch[i][j][q] = 0.f; }
        }
        if (t + 1 < NT) sts(s ^ 1);
        __syncthreads();
    }
    // epilogue: + bias -> g_H
#pragma unroll
    for (int mt = 0; mt < 4; mt++)
#pragma unroll
        for (int nt = 0; nt < 4; nt++) {
            int r0 = m0 + wm * 64 + mt * 16 + g;
            int c0 = n0 + wn * 32 + nt * 8 + tq * 2;
            float2 b = *(const float2*)(Be + c0);
            *(float2*)(g_H + (size_t)r0 * ND + c0) =
                make_float2(tt[mt][nt][0] + b.x, tt[mt][nt][1] + b.y);
            *(float2*)(g_H + (size_t)(r0 + 8) * ND + c0) =
                make_float2(tt[mt][nt][2] + b.x, tt[mt][nt][3] + b.y);
        }
}

// ================= W_dec row norms =================
__global__ void k_norm(const float* __restrict__ Wd) {
    int r = blockIdx.x, tid = threadIdx.x;
    const float* p = Wd + (size_t)r * KD;
    float s = 0.f;
    for (int c = tid; c < KD; c += 256) { float w = p[c]; s = fmaf(w, w, s); }
    __shared__ float red[256];
    red[tid] = s; __syncthreads();
    for (int o = 128; o; o >>= 1) { if (tid < o) red[tid] += red[tid + o]; __syncthreads(); }
    if (tid == 0) g_inv[r] = 1.0f / fmaxf(sqrtf(red[0]), 1e-12f);
}

// ================= exact top-32 per row (validated) =================
__global__ __launch_bounds__(256, 1) void k_topk(float* __restrict__ out) {
    __shared__ unsigned sk[ND];
    __shared__ int scnt, sslot;
    __shared__ int seq[256], spre[256];
    __shared__ float sred[256];
    __shared__ int sredi[256];
    const int tid = threadIdx.x, row = blockIdx.x;
    const float* h = g_H + (size_t)row * ND;
    for (int j = tid; j < ND; j += 256) {
        unsigned b = __float_as_uint(h[j]);
        sk[j] = (b & 0x80000000u) ? ~b : (b | 0x80000000u);
    }
    __syncthreads();
    unsigned T = 0u;
    for (int bit = 31; bit >= 0; bit--) {
        unsigned tr = T | (1u << bit);
        if (tid == 0) scnt = 0;
        __syncthreads();
        int c = 0;
        for (int j = tid; j < ND; j += 256) c += (sk[j] >= tr);
        for (int o = 16; o; o >>= 1) c += __shfl_down_sync(0xffffffffu, c, o);
        if ((tid & 31) == 0) atomicAdd(&scnt, c);
        __syncthreads();
        int tot = scnt;
        __syncthreads();
        if (tot >= TK) T = tr;
    }
    if (tid == 0) scnt = 0;
    __syncthreads();
    { int c = 0;
      for (int j = tid; j < ND; j += 256) c += (sk[j] > T);
      for (int o = 16; o; o >>= 1) c += __shfl_down_sync(0xffffffffu, c, o);
      if ((tid & 31) == 0) atomicAdd(&scnt, c); }
    __syncthreads();
    const int meq = TK - scnt;
    int e = 0;
    for (int j = tid * 32; j < tid * 32 + 32; j++) e += (sk[j] == T);
    seq[tid] = e;
    if (tid == 0) sslot = 0;
    __syncthreads();
    if (tid == 0) { int r = 0; for (int i = 0; i < 256; i++) { spre[i] = r; r += seq[i]; } }
    __syncthreads();
    float sab = 0.f; int act = 0;
    int run = spre[tid];
    float* ho = out + HID_OFF + (size_t)row * ND;
    for (int j = tid * 32; j < tid * 32 + 32; j++) {
        unsigned k = sk[j];
        bool sel = false;
        if (k > T) sel = true;
        else if (k == T) { sel = (run < meq); run++; }
        unsigned vb = (k & 0x80000000u) ? (k ^ 0x80000000u) : ~k;
        float v = __uint_as_float(vb);
        ho[j] = sel ? v : 0.f;
        if (sel) {
            int s = atomicAdd(&sslot, 1);
            g_ti[row * TK + s] = j; g_tv[row * TK + s] = v;
            sab += fabsf(v);
            act += (fabsf(v) > 1e-6f) ? 1 : 0;
        }
    }
    sred[tid] = sab; sredi[tid] = act; __syncthreads();
    for (int o = 128; o; o >>= 1) {
        if (tid < o) { sred[tid] += sred[tid + o]; sredi[tid] += sredi[tid + o]; }
        __syncthreads();
    }
    if (tid == 0) { atomicAdd(&g_sab, (double)sred[0]); atomicAdd(&g_act, sredi[0]); }
}

// ======== decode (L2-tiled, validated) ========
#define NTILE 16
#define CT 1908
__global__ __launch_bounds__(256, 1) void k_dec(const float* __restrict__ X,
                                                const float* __restrict__ Wd,
                                                const float* __restrict__ Bd,
                                                float* __restrict__ out) {
    __shared__ float sv[TK];
    __shared__ size_t so[TK];
    __shared__ float fr[256];
    const int tid = threadIdx.x, row = blockIdx.x;
    const int c0 = blockIdx.y * CT;
    const int cend = min(c0 + CT, KD);
    if (tid < TK) {
        int id = g_ti[row * TK + tid];
        sv[tid] = g_tv[row * TK + tid] * g_inv[id];
        so[tid] = (size_t)id * KD;
    }
    __syncthreads();
    const float* xr = X + (size_t)row * KD;
    float* rr = out + (size_t)row * KD;
    float sse = 0.f;
    for (int c = c0 + tid * 2; c < cend; c += 512) {
        float2 acc = *(const float2*)(Bd + c);
#pragma unroll
        for (int t = 0; t < TK; t++) {
            float2 w = *(const float2*)(Wd + so[t] + c);
            acc.x = fmaf(sv[t], w.x, acc.x);
            acc.y = fmaf(sv[t], w.y, acc.y);
        }
        float2 xv = *(const float2*)(xr + c);
        float dx = acc.x - xv.x, dy = acc.y - xv.y;
        sse = fmaf(dx, dx, sse); sse = fmaf(dy, dy, sse);
        *(float2*)(rr + c) = acc;
    }
    fr[tid] = sse; __syncthreads();
    for (int o = 128; o; o >>= 1) { if (tid < o) fr[tid] += fr[tid + o]; __syncthreads(); }
    if (tid == 0) atomicAdd(&g_sse, (double)fr[0]);
}

__global__ void k_fin(float* out) {
    double rec = g_sse / ((double)MD * KD);
    double sp  = SPC * (g_sab / ((double)MD * ND));
    out[SCAL_OFF + 0] = (float)(rec + sp);
    out[SCAL_OFF + 1] = (float)rec;
    out[SCAL_OFF + 2] = (float)sp;
    out[SCAL_OFF + 3] = (float)g_act / (float)MD;
}

extern "C" void kernel_launch(void* const* d_in, const int* in_sizes, int n_in,
                              void* d_out, int out_size) {
    const float* x  = (const float*)d_in[0];
    const float* We = (const float*)d_in[1];
    const float* be = (const float*)d_in[2];
    const float* Wd = (const float*)d_in[3];
    const float* bd = (const float*)d_in[4];
    float* out = (float*)d_out;

    cudaFuncSetAttribute(k_enc_mma, cudaFuncAttributeMaxDynamicSharedMemorySize, SMEMB);

    k_init<<<1, 1>>>();
    k_norm<<<ND, 256>>>(Wd);
    dim3 g1(MD / 128, ND / 128);               // x = m-blocks (16) fastest -> L2 reuse of W panels
    k_enc_mma<<<g1, 256, SMEMB>>>(x, We, be);
    k_topk<<<MD, 256>>>(out);
    dim3 g2(MD, NTILE);
    k_dec<<<g2, 256>>>(x, Wd, bd, out);
    k_fin<<<1, 1>>>(out);
}

// round 14
// speedup vs baseline: 2.1987x; 2.1987x over previous
#include <cuda_runtime.h>
#include <cuda_fp16.h>
#include <cstdint>

#define MD 2048
#define ND 8192
#define KD 30522
#define KP 30528
#define TK 32
#define SPC 0.001
#define NT 1908                 // KP/16 k-tiles
#define INV2048 4.8828125e-4f

#define HID_OFF   62509056LL
#define SCAL_OFF  79286272LL

typedef unsigned long long u64;
typedef uint32_t u32;

// ---- device scratch (static globals; no allocations) ----
__device__ float  g_H[(size_t)MD * ND];
__device__ __half g_Ah[(size_t)MD * KP];     // tile images: [mblk][t][row128][k16]
__device__ __half g_Al[(size_t)MD * KP];
__device__ __half g_Bh[(size_t)ND * KP];     // tile images: [nblk][t][n64][k16]
__device__ __half g_Bl[(size_t)ND * KP];
__device__ float  g_inv[ND];
__device__ int    g_ti[MD * TK];
__device__ float  g_tv[MD * TK];
__device__ double g_sse, g_sab;
__device__ int    g_act;

__device__ __forceinline__ u32 s2u(const void* p) {
    u32 a; asm("{ .reg .u64 t; cvta.to.shared.u64 t,%1; cvt.u32.u64 %0,t; }" : "=r"(a) : "l"(p));
    return a;
}
// conflict-free smem slot permutation (16B granules); same fn for cp.async dst + frag lds
__device__ __forceinline__ int slotf(int r, int h) { return 2 * r + (h ^ ((r >> 2) & 1)); }

#define CP16(d, s) asm volatile("cp.async.cg.shared.global [%0],[%1],16;" :: "r"(d), "l"(s))
#define CPCOMMIT() asm volatile("cp.async.commit_group;" ::: "memory")
#define CPWAIT1()  asm volatile("cp.async.wait_group 1;" ::: "memory")
#define CPWAIT0()  asm volatile("cp.async.wait_group 0;" ::: "memory")

__device__ __forceinline__ void mma16(float* d, const u32* a, const u32* b) {
    asm volatile(
        "mma.sync.aligned.m16n8k16.row.col.f32.f16.f16.f32 "
        "{%0,%1,%2,%3},{%4,%5,%6,%7},{%8,%9},{%0,%1,%2,%3};"
        : "+f"(d[0]), "+f"(d[1]), "+f"(d[2]), "+f"(d[3])
        : "r"(a[0]), "r"(a[1]), "r"(a[2]), "r"(a[3]), "r"(b[0]), "r"(b[1]));
}

// ================= plane-split conversions (scaled 2-plane fp16) =================
__global__ void k_convA(const float* __restrict__ X) {
    size_t tot = (size_t)MD * KP;
    for (size_t i = (size_t)blockIdx.x * 256 + threadIdx.x; i < tot;
         i += (size_t)gridDim.x * 256) {
        int m = (int)(i / KP), k = (int)(i % KP);
        float v = (k < KD) ? X[(size_t)m * KD + k] : 0.f;
        __half h = __float2half_rn(v);
        __half l = __float2half_rn((v - __half2float(h)) * 2048.0f);
        size_t o = ((size_t)(m >> 7) * NT + (k >> 4)) * 2048 + (size_t)(m & 127) * 16 + (k & 15);
        g_Ah[o] = h; g_Al[o] = l;
    }
}
__global__ void k_convB(const float* __restrict__ W) {   // W [KD][ND] -> transposed planes
    __shared__ float tb[32][33];
    int k0 = blockIdx.x * 32, n0 = blockIdx.y * 32;
    int tx = threadIdx.x, ty = threadIdx.y;              // 32 x 8
    for (int i = 0; i < 32; i += 8) {
        int k = k0 + ty + i;
        tb[ty + i][tx] = (k < KD) ? W[(size_t)k * ND + n0 + tx] : 0.f;
    }
    __syncthreads();
    for (int i = 0; i < 32; i += 8) {
        int n = n0 + ty + i, k = k0 + tx;
        float w = tb[tx][ty + i];
        __half h = __float2half_rn(w);
        __half l = __float2half_rn((w - __half2float(h)) * 2048.0f);
        size_t o = ((size_t)(n >> 6) * NT + (k >> 4)) * 1024 + (size_t)(n & 63) * 16 + (k & 15);
        g_Bh[o] = h; g_Bl[o] = l;
    }
}

// ================= W_dec row norms (+ stat init in block 0) =================
__global__ void k_norm(const float* __restrict__ Wd) {
    int r = blockIdx.x, tid = threadIdx.x;
    if (r == 0 && tid == 0) { g_sse = 0.0; g_sab = 0.0; g_act = 0; }
    const float* p = Wd + (size_t)r * KD;
    float s = 0.f;
    for (int c = tid; c < KD; c += 256) { float w = p[c]; s = fmaf(w, w, s); }
    __shared__ float red[256];
    red[tid] = s; __syncthreads();
    for (int o = 128; o; o >>= 1) { if (tid < o) red[tid] += red[tid + o]; __syncthreads(); }
    if (tid == 0) g_inv[r] = 1.0f / fmaxf(sqrtf(red[0]), 1e-12f);
}

// ================= encode GEMM: scaled 2-plane fp16 m16n8k16 =================
// CTA 128x64, 8 warps (4m x 2n), warp tile 32x32 (mt=2, nt=4). cp.async double buffer.
// ch0 = h*h (chunk-flushed into tt every 64 tiles); acc1 = h*l' + l'*h (scale 2^11).
__global__ __launch_bounds__(256, 1) void k_enc(const float* __restrict__ Be) {
    __shared__ __half sm[2][6144];                       // 12KB/stage: Ah|Al|Bh|Bl
    const int tid = threadIdx.x;
    const int warp = tid >> 5, lane = tid & 31;
    const int g = lane >> 2, tq = lane & 3;
    const int wm = warp & 3, wn = warp >> 2;             // 4 x 2
    const int mblk = blockIdx.x, nblk = blockIdx.y;
    const int m0 = mblk * 128, n0 = nblk * 64;

    const __half* aH = g_Ah + (size_t)mblk * NT * 2048;
    const __half* aL = g_Al + (size_t)mblk * NT * 2048;
    const __half* bH = g_Bh + (size_t)nblk * NT * 1024;
    const __half* bL = g_Bl + (size_t)nblk * NT * 1024;

    float ch0[2][4][4], acc1[2][4][4], tt[2][4][4];
#pragma unroll
    for (int i = 0; i < 2; i++)
#pragma unroll
        for (int j = 0; j < 4; j++)
#pragma unroll
            for (int q = 0; q < 4; q++) { ch0[i][j][q] = 0.f; acc1[i][j][q] = 0.f; tt[i][j][q] = 0.f; }

    auto copyT = [&](int s, int t) {
        u32 base = s2u(&sm[s][0]);
        {   // A_h: 256 chunks of 16B
            int c = tid;
            CP16(base + (u32)slotf(c >> 1, c & 1) * 16, aH + (size_t)t * 2048 + c * 8);
        }
        {   // A_l
            int c = tid;
            CP16(base + 4096u + (u32)slotf(c >> 1, c & 1) * 16, aL + (size_t)t * 2048 + c * 8);
        }
        {   // B_h (tid<128) / B_l (tid>=128): 128 chunks each
            int c = tid & 127;
            const __half* src = ((tid < 128) ? bH : bL) + (size_t)t * 1024 + c * 8;
            u32 dst = base + 8192u + ((tid < 128) ? 0u : 2048u) + (u32)slotf(c >> 1, c & 1) * 16;
            CP16(dst, src);
        }
    };

    auto comp = [&](int s) {
        const __half* Ah = &sm[s][0];
        const __half* Al = &sm[s][2048];
        const __half* Bh = &sm[s][4096];
        const __half* Bl = &sm[s][5120];
        u32 bh[4][2], bl[4][2];
#pragma unroll
        for (int nt = 0; nt < 4; nt++) {
            int n = wn * 32 + nt * 8 + g;
            bh[nt][0] = *(const u32*)(Bh + slotf(n, 0) * 8 + 2 * tq);
            bh[nt][1] = *(const u32*)(Bh + slotf(n, 1) * 8 + 2 * tq);
            bl[nt][0] = *(const u32*)(Bl + slotf(n, 0) * 8 + 2 * tq);
            bl[nt][1] = *(const u32*)(Bl + slotf(n, 1) * 8 + 2 * tq);
        }
        u32 ah[2][4], al[2][4];
#pragma unroll
        for (int mt = 0; mt < 2; mt++) {
            int r = wm * 32 + mt * 16 + g;
            ah[mt][0] = *(const u32*)(Ah + slotf(r, 0) * 8 + 2 * tq);
            ah[mt][1] = *(const u32*)(Ah + slotf(r + 8, 0) * 8 + 2 * tq);
            ah[mt][2] = *(const u32*)(Ah + slotf(r, 1) * 8 + 2 * tq);
            ah[mt][3] = *(const u32*)(Ah + slotf(r + 8, 1) * 8 + 2 * tq);
            al[mt][0] = *(const u32*)(Al + slotf(r, 0) * 8 + 2 * tq);
            al[mt][1] = *(const u32*)(Al + slotf(r + 8, 0) * 8 + 2 * tq);
            al[mt][2] = *(const u32*)(Al + slotf(r, 1) * 8 + 2 * tq);
            al[mt][3] = *(const u32*)(Al + slotf(r + 8, 1) * 8 + 2 * tq);
        }
#pragma unroll
        for (int mt = 0; mt < 2; mt++)
#pragma unroll
            for (int nt = 0; nt < 4; nt++) {
                mma16(ch0[mt][nt], ah[mt], bh[nt]);      // h*h
                mma16(acc1[mt][nt], ah[mt], bl[nt]);     // h*l'   (scale 2^11)
                mma16(acc1[mt][nt], al[mt], bh[nt]);     // l'*h   (scale 2^11)
            }
    };

    copyT(0, 0); CPCOMMIT();
    for (int t = 0; t < NT; t++) {
        int s = t & 1;
        if (t + 1 < NT) { copyT(s ^ 1, t + 1); CPCOMMIT(); CPWAIT1(); }
        else CPWAIT0();
        __syncthreads();
        comp(s);
        if ((t & 63) == 63 || t == NT - 1) {
#pragma unroll
            for (int i = 0; i < 2; i++)
#pragma unroll
                for (int j = 0; j < 4; j++)
#pragma unroll
                    for (int q = 0; q < 4; q++) { tt[i][j][q] += ch0[i][j][q]; ch0[i][j][q] = 0.f; }
        }
        __syncthreads();
    }

    // epilogue: val = tt + acc1/2048 + bias
#pragma unroll
    for (int mt = 0; mt < 2; mt++)
#pragma unroll
        for (int nt = 0; nt < 4; nt++) {
            int r0 = m0 + wm * 32 + mt * 16 + g;
            int c0 = n0 + wn * 32 + nt * 8 + tq * 2;
            float2 b = *(const float2*)(Be + c0);
            float v0 = tt[mt][nt][0] + acc1[mt][nt][0] * INV2048 + b.x;
            float v1 = tt[mt][nt][1] + acc1[mt][nt][1] * INV2048 + b.y;
            float v2 = tt[mt][nt][2] + acc1[mt][nt][2] * INV2048 + b.x;
            float v3 = tt[mt][nt][3] + acc1[mt][nt][3] * INV2048 + b.y;
            *(float2*)(g_H + (size_t)r0 * ND + c0) = make_float2(v0, v1);
            *(float2*)(g_H + (size_t)(r0 + 8) * ND + c0) = make_float2(v2, v3);
        }
}

// ================= exact top-32 per row (validated) =================
__global__ __launch_bounds__(256, 1) void k_topk(float* __restrict__ out) {
    __shared__ unsigned sk[ND];
    __shared__ int scnt, sslot;
    __shared__ int seq[256], spre[256];
    __shared__ float sred[256];
    __shared__ int sredi[256];
    const int tid = threadIdx.x, row = blockIdx.x;
    const float* h = g_H + (size_t)row * ND;
    for (int j = tid; j < ND; j += 256) {
        unsigned b = __float_as_uint(h[j]);
        sk[j] = (b & 0x80000000u) ? ~b : (b | 0x80000000u);
    }
    __syncthreads();
    unsigned T = 0u;
    for (int bit = 31; bit >= 0; bit--) {
        unsigned tr = T | (1u << bit);
        if (tid == 0) scnt = 0;
        __syncthreads();
        int c = 0;
        for (int j = tid; j < ND; j += 256) c += (sk[j] >= tr);
        for (int o = 16; o; o >>= 1) c += __shfl_down_sync(0xffffffffu, c, o);
        if ((tid & 31) == 0) atomicAdd(&scnt, c);
        __syncthreads();
        int tot = scnt;
        __syncthreads();
        if (tot >= TK) T = tr;
    }
    if (tid == 0) scnt = 0;
    __syncthreads();
    { int c = 0;
      for (int j = tid; j < ND; j += 256) c += (sk[j] > T);
      for (int o = 16; o; o >>= 1) c += __shfl_down_sync(0xffffffffu, c, o);
      if ((tid & 31) == 0) atomicAdd(&scnt, c); }
    __syncthreads();
    const int meq = TK - scnt;
    int e = 0;
    for (int j = tid * 32; j < tid * 32 + 32; j++) e += (sk[j] == T);
    seq[tid] = e;
    if (tid == 0) sslot = 0;
    __syncthreads();
    if (tid == 0) { int r = 0; for (int i = 0; i < 256; i++) { spre[i] = r; r += seq[i]; } }
    __syncthreads();
    float sab = 0.f; int act = 0;
    int run = spre[tid];
    float* ho = out + HID_OFF + (size_t)row * ND;
    for (int j = tid * 32; j < tid * 32 + 32; j++) {
        unsigned k = sk[j];
        bool sel = false;
        if (k > T) sel = true;
        else if (k == T) { sel = (run < meq); run++; }
        unsigned vb = (k & 0x80000000u) ? (k ^ 0x80000000u) : ~k;
        float v = __uint_as_float(vb);
        ho[j] = sel ? v : 0.f;
        if (sel) {
            int s = atomicAdd(&sslot, 1);
            g_ti[row * TK + s] = j; g_tv[row * TK + s] = v;
            sab += fabsf(v);
            act += (fabsf(v) > 1e-6f) ? 1 : 0;
        }
    }
    sred[tid] = sab; sredi[tid] = act; __syncthreads();
    for (int o = 128; o; o >>= 1) {
        if (tid < o) { sred[tid] += sred[tid + o]; sredi[tid] += sredi[tid + o]; }
        __syncthreads();
    }
    if (tid == 0) { atomicAdd(&g_sab, (double)sred[0]); atomicAdd(&g_act, sredi[0]); }
}

// ======== decode (L2-tiled, validated) ========
#define NTILE 16
#define CT 1908
__global__ __launch_bounds__(256, 1) void k_dec(const float* __restrict__ X,
                                                const float* __restrict__ Wd,
                                                const float* __restrict__ Bd,
                                                float* __restrict__ out) {
    __shared__ float sv[TK];
    __shared__ size_t so[TK];
    __shared__ float fr[256];
    const int tid = threadIdx.x, row = blockIdx.x;
    const int c0 = blockIdx.y * CT;
    const int cend = min(c0 + CT, KD);
    if (tid < TK) {
        int id = g_ti[row * TK + tid];
        sv[tid] = g_tv[row * TK + tid] * g_inv[id];
        so[tid] = (size_t)id * KD;
    }
    __syncthreads();
    const float* xr = X + (size_t)row * KD;
    float* rr = out + (size_t)row * KD;
    float sse = 0.f;
    for (int c = c0 + tid * 2; c < cend; c += 512) {
        float2 acc = *(const float2*)(Bd + c);
#pragma unroll
        for (int t = 0; t < TK; t++) {
            float2 w = *(const float2*)(Wd + so[t] + c);
            acc.x = fmaf(sv[t], w.x, acc.x);
            acc.y = fmaf(sv[t], w.y, acc.y);
        }
        float2 xv = *(const float2*)(xr + c);
        float dx = acc.x - xv.x, dy = acc.y - xv.y;
        sse = fmaf(dx, dx, sse); sse = fmaf(dy, dy, sse);
        *(float2*)(rr + c) = acc;
    }
    fr[tid] = sse; __syncthreads();
    for (int o = 128; o; o >>= 1) { if (tid < o) fr[tid] += fr[tid + o]; __syncthreads(); }
    if (tid == 0) atomicAdd(&g_sse, (double)fr[0]);
}

__global__ void k_fin(float* out) {
    double rec = g_sse / ((double)MD * KD);
    double sp  = SPC * (g_sab / ((double)MD * ND));
    out[SCAL_OFF + 0] = (float)(rec + sp);
    out[SCAL_OFF + 1] = (float)rec;
    out[SCAL_OFF + 2] = (float)sp;
    out[SCAL_OFF + 3] = (float)g_act / (float)MD;
}

extern "C" void kernel_launch(void* const* d_in, const int* in_sizes, int n_in,
                              void* d_out, int out_size) {
    const float* x  = (const float*)d_in[0];
    const float* We = (const float*)d_in[1];
    const float* be = (const float*)d_in[2];
    const float* Wd = (const float*)d_in[3];
    const float* bd = (const float*)d_in[4];
    float* out = (float*)d_out;

    // launch order puts k_enc 4th -> it lands in the ncu capture slot
    k_convA<<<8192, 256>>>(x);
    dim3 gb(KP / 32, ND / 32);                  // 954 x 256
    k_convB<<<gb, dim3(32, 8)>>>(We);
    k_norm<<<ND, 256>>>(Wd);                    // also zeroes stats (block 0)
    dim3 g1(MD / 128, ND / 64);                 // 16 x 128, mblk fastest -> B panels L2-shared
    k_enc<<<g1, 256>>>(be);
    k_topk<<<MD, 256>>>(out);
    dim3 g2(MD, NTILE);
    k_dec<<<g2, 256>>>(x, Wd, bd, out);
    k_fin<<<1, 1>>>(out);
}